// round 17
// baseline (speedup 1.0000x reference)
#include <cuda_runtime.h>
#include <cuda_bf16.h>
#include <mma.h>
#include <cstdint>
#include <cstddef>

using namespace nvcuda;

// ---------------------------------------------------------------------------
// Dims
// ---------------------------------------------------------------------------
#define B_  32
#define C_  512
#define NA_ 441
#define K1_ (27*512)         // 13824
#define K2_ (144*512)        // 73728
#define NC1 216              // 27 taps * 8 ic-chunks (64 ch)
#define NC2 288              // 36 taps * 8 ic-chunks (per k-split of 4)

// output layout: rois [32,300,5] | cls_prob [32,18,7,7] | bbox_pred [32,36,7,7]
#define ROIS_OFF 0
#define CLS_OFF  48000
#define BBOX_OFF 76224

// smem (bytes): 144B pitch rows (72 bf16), 3 planes per operand
#define LDMA 72
#define SA_H 0u
#define SA_M 18432u
#define SA_L 36864u          // A: 128 rows * 144 per plane
#define SB_H 55296u
#define SB_M 64512u
#define SB_L 73728u          // B: 64 rows * 144 per plane
#define CBUF 82944u
#define SMEM_CONV (2*CBUF)   // 165888

typedef wmma::fragment<wmma::matrix_a, 16, 16, 16, __nv_bfloat16, wmma::row_major> FragA;
typedef wmma::fragment<wmma::matrix_b, 16, 16, 16, __nv_bfloat16, wmma::col_major> FragB;
typedef wmma::fragment<wmma::accumulator, 16, 16, 16, float> FragC;

// ---------------------------------------------------------------------------
// Scratch (static device globals)
// ---------------------------------------------------------------------------
__device__ __nv_bfloat16 g_w1h[(size_t)C_*K1_], g_w1m[(size_t)C_*K1_], g_w1l[(size_t)C_*K1_];
__device__ __nv_bfloat16 g_w2h[(size_t)C_*K2_], g_w2m[(size_t)C_*K2_], g_w2l[(size_t)C_*K2_];
__device__ __nv_bfloat16 g_x1h[(size_t)B_*18*100*C_], g_x1m[(size_t)B_*18*100*C_], g_x1l[(size_t)B_*18*100*C_];
__device__ __nv_bfloat16 g_x2h[(size_t)B_*16*100*C_], g_x2m[(size_t)B_*16*100*C_], g_x2l[(size_t)B_*16*100*C_];
__device__ float g_p2[(size_t)4*B_*C_*49];
__device__ float g_prop[B_*NA_*4];
__device__ float g_scr [B_*NA_];

__constant__ float c_anch[9][4] = {
    {-38.f,  -16.f,  53.f,  31.f},
    {-84.f,  -40.f,  99.f,  55.f},
    {-176.f, -88.f,  191.f, 103.f},
    {-24.f,  -24.f,  39.f,  39.f},
    {-56.f,  -56.f,  71.f,  71.f},
    {-120.f, -120.f, 135.f, 135.f},
    {-14.f,  -36.f,  29.f,  51.f},
    {-36.f,  -80.f,  51.f,  95.f},
    {-80.f,  -168.f, 95.f,  183.f}};

// ---------------------------------------------------------------------------
// PTX helpers
// ---------------------------------------------------------------------------
__device__ __forceinline__ void cpa16(unsigned dst, const void* src) {
    asm volatile("cp.async.cg.shared.global [%0],[%1],16;" :: "r"(dst), "l"(src));
}
__device__ __forceinline__ void cpcommit() { asm volatile("cp.async.commit_group;"); }
__device__ __forceinline__ void cpwait1()  { asm volatile("cp.async.wait_group 1;" ::: "memory"); }
__device__ __forceinline__ void cpwait0()  { asm volatile("cp.async.wait_group 0;" ::: "memory"); }

// 3-way bf16 split: v = h + m + l + O(2^-26 v); every issued product exact
__device__ __forceinline__ void bsplit3(float v, __nv_bfloat16& h,
                                        __nv_bfloat16& m, __nv_bfloat16& l) {
    h = __float2bfloat16(v);
    float r = v - __bfloat162float(h);
    m = __float2bfloat16(r);
    float r2 = r - __bfloat162float(m);
    l = __float2bfloat16(r2);
}

// 6 exact passes into a ZEROED temp frag (breaks long RZ accumulation chains),
// then RN FADD into per-thread register sums.
__device__ __forceinline__ void mma6_flush(float* sums, FragC& t,
                                           const FragA& ah, const FragA& am,
                                           const FragA& al, const FragB& bh,
                                           const FragB& bm, const FragB& bl) {
    wmma::fill_fragment(t, 0.f);
    wmma::mma_sync(t, ah, bh, t);
    wmma::mma_sync(t, am, bh, t);
    wmma::mma_sync(t, ah, bm, t);
    wmma::mma_sync(t, am, bm, t);
    wmma::mma_sync(t, ah, bl, t);
    wmma::mma_sync(t, al, bh, t);
#pragma unroll
    for (int e = 0; e < t.num_elements; ++e) sums[e] += t.x[e];
}

// ---------------------------------------------------------------------------
// Prep: weights [oc][ic][TAPS] fp32 -> h/m/l bf16 [oc][tap*512+ic]
// ---------------------------------------------------------------------------
__global__ void prep_w(const float* __restrict__ w,
                       __nv_bfloat16* __restrict__ oh,
                       __nv_bfloat16* __restrict__ om,
                       __nv_bfloat16* __restrict__ ol, int TAPS) {
    __shared__ float s[64][145];
    int oc = blockIdx.x, it = blockIdx.y;
    size_t K = (size_t)TAPS * 512;
    const float* src = w + ((size_t)oc * 512 + it * 64) * TAPS;
    for (int i = threadIdx.x; i < 64 * TAPS; i += blockDim.x) {
        int ic = i / TAPS, tp = i - ic * TAPS;
        s[ic][tp] = src[(size_t)ic * TAPS + tp];
    }
    __syncthreads();
    for (int j = threadIdx.x; j < TAPS * 64; j += blockDim.x) {
        int tp = j >> 6, ic = j & 63;
        __nv_bfloat16 h, m, l;
        bsplit3(s[ic][tp], h, m, l);
        size_t o = (size_t)oc * K + (size_t)tp * 512 + it * 64 + ic;
        oh[o] = h; om[o] = m; ol[o] = l;
    }
}

// zero padded activation planes (borders must stay zero every replay)
__global__ void zero_x1k() {
    size_t i = (size_t)blockIdx.x * 256 + threadIdx.x;
    uint4 z = make_uint4(0, 0, 0, 0);
    ((uint4*)g_x1h)[i] = z; ((uint4*)g_x1m)[i] = z; ((uint4*)g_x1l)[i] = z;
}
__global__ void zero_x2k() {
    size_t i = (size_t)blockIdx.x * 256 + threadIdx.x;
    uint4 z = make_uint4(0, 0, 0, 0);
    ((uint4*)g_x2h)[i] = z; ((uint4*)g_x2m)[i] = z; ((uint4*)g_x2l)[i] = z;
}

// input -> channels-last padded planes [b][t+1][100][512] h/m/l (interior only)
__global__ void prep_x1(const float* __restrict__ bf) {
    __shared__ float s[64][50];
    int b = blockIdx.x, t = blockIdx.y, it = blockIdx.z;
    const float* src = bf + (((size_t)b * 512 + it * 64) * 16 + t) * 49;
    for (int i = threadIdx.x; i < 64 * 49; i += 256) {
        int ic = i / 49, p = i - ic * 49;
        s[ic][p] = src[(size_t)ic * 784 + p];
    }
    __syncthreads();
    for (int j = threadIdx.x; j < 49 * 64; j += 256) {
        int p = j >> 6, ic = j & 63;
        __nv_bfloat16 h, m, l;
        bsplit3(s[ic][p], h, m, l);
        int pos = (p / 7 + 1) * 10 + (p % 7) + 1;
        size_t o = (((size_t)b * 18 + t + 1) * 100 + pos) * 512 + it * 64 + ic;
        g_x1h[o] = h; g_x1m[o] = m; g_x1l[o] = l;
    }
}

// ---------------------------------------------------------------------------
// Conv1 GEMM (wmma, per-k16 accumulator flush): grid (4, 512), 128 thr.
// CTA: M=128 oc x N=64 pos; warp: M=32 x N=64. K chunks of 64 ch.
// ---------------------------------------------------------------------------
__global__ __launch_bounds__(128) void conv1_mma(const float* __restrict__ bias) {
    extern __shared__ char smem[];
    const unsigned smb = (unsigned)__cvta_generic_to_shared(smem);
    const int tid = threadIdx.x, wid = tid >> 5;
    const int octile = blockIdx.x, plane = blockIdx.y;
    const int b = plane >> 4, t = plane & 15;

    float sums[2][4][8];
#pragma unroll
    for (int mt = 0; mt < 2; ++mt)
#pragma unroll
        for (int nt = 0; nt < 4; ++nt)
#pragma unroll
            for (int e = 0; e < 8; ++e) sums[mt][nt][e] = 0.f;

    auto stage = [&](int ci, int buf) {
        int tap = ci >> 3, icc = ci & 7;
        int dt = tap / 9, dh = (tap % 9) / 3, dw = tap % 3;
        unsigned bb = smb + (unsigned)buf * CBUF;
        size_t koff = (size_t)tap * 512 + icc * 64;
        const __nv_bfloat16* ah = g_w1h + (size_t)(octile * 128) * K1_ + koff;
        const __nv_bfloat16* am = g_w1m + (size_t)(octile * 128) * K1_ + koff;
        const __nv_bfloat16* al = g_w1l + (size_t)(octile * 128) * K1_ + koff;
        for (int i = tid; i < 1024; i += 128) {
            int r = i >> 3, c = i & 7;
            unsigned d = (unsigned)(r * 144 + c * 16);
            size_t so = (size_t)r * K1_ + c * 8;
            cpa16(bb + SA_H + d, ah + so);
            cpa16(bb + SA_M + d, am + so);
            cpa16(bb + SA_L + d, al + so);
        }
        size_t xoff = ((size_t)(b * 18 + t + dt) * 100) * 512 + icc * 64;
        for (int i = tid; i < 512; i += 128) {
            int n = i >> 3, c = i & 7;
            int h = n >> 3, w = n & 7;
            size_t so = xoff + (size_t)((h + dh) * 10 + (w + dw)) * 512 + c * 8;
            unsigned d = (unsigned)(n * 144 + c * 16);
            cpa16(bb + SB_H + d, g_x1h + so);
            cpa16(bb + SB_M + d, g_x1m + so);
            cpa16(bb + SB_L + d, g_x1l + so);
        }
    };

    auto comp = [&](int buf) {
        char* base = smem + (size_t)buf * CBUF;
        const __nv_bfloat16* pah = (const __nv_bfloat16*)(base + SA_H);
        const __nv_bfloat16* pam = (const __nv_bfloat16*)(base + SA_M);
        const __nv_bfloat16* pal = (const __nv_bfloat16*)(base + SA_L);
        const __nv_bfloat16* pbh = (const __nv_bfloat16*)(base + SB_H);
        const __nv_bfloat16* pbm = (const __nv_bfloat16*)(base + SB_M);
        const __nv_bfloat16* pbl = (const __nv_bfloat16*)(base + SB_L);
        FragC tf;
#pragma unroll
        for (int k16 = 0; k16 < 4; ++k16) {
            int ko = k16 * 16;
#pragma unroll
            for (int mt = 0; mt < 2; ++mt) {
                int ar = (wid * 32 + mt * 16) * LDMA + ko;
                FragA ah, am, al;
                wmma::load_matrix_sync(ah, pah + ar, LDMA);
                wmma::load_matrix_sync(am, pam + ar, LDMA);
                wmma::load_matrix_sync(al, pal + ar, LDMA);
#pragma unroll
                for (int nt = 0; nt < 4; ++nt) {
                    int br = (nt * 16) * LDMA + ko;
                    FragB bh, bm, bl;
                    wmma::load_matrix_sync(bh, pbh + br, LDMA);
                    wmma::load_matrix_sync(bm, pbm + br, LDMA);
                    wmma::load_matrix_sync(bl, pbl + br, LDMA);
                    mma6_flush(sums[mt][nt], tf, ah, am, al, bh, bm, bl);
                }
            }
        }
    };

    stage(0, 0); cpcommit();
    stage(1, 1); cpcommit();
#pragma unroll 1
    for (int ci = 0; ci < NC1; ++ci) {
        if (ci + 1 < NC1) cpwait1(); else cpwait0();
        __syncthreads();
        comp(ci & 1);
        __syncthreads();
        if (ci + 2 < NC1) { stage(ci + 2, ci & 1); cpcommit(); }
    }

    // epilogue: move sums into frags, canonical store, scalar scatter
    __syncthreads();
    float* st = (float*)smem;   // 128 x 64 fp32 = 32KB
    {
        FragC of;
#pragma unroll
        for (int mt = 0; mt < 2; ++mt)
#pragma unroll
            for (int nt = 0; nt < 4; ++nt) {
#pragma unroll
                for (int e = 0; e < of.num_elements; ++e) of.x[e] = sums[mt][nt][e];
                wmma::store_matrix_sync(st + (wid * 32 + mt * 16) * 64 + nt * 16,
                                        of, 64, wmma::mem_row_major);
            }
    }
    __syncthreads();
    for (int e = tid; e < 8192; e += 128) {
        int row = e >> 6, n = e & 63;
        int h = n >> 3, w = n & 7;
        if (h < 7 && w < 7) {
            int oc = octile * 128 + row;
            float v = fmaxf(st[e] + bias[oc], 0.f);
            __nv_bfloat16 hh, mm, ll;
            bsplit3(v, hh, mm, ll);
            size_t o = (((size_t)(b * 16 + t) * 100) + (h + 1) * 10 + (w + 1)) * 512 + oc;
            g_x2h[o] = hh; g_x2m[o] = mm; g_x2l[o] = ll;
        }
    }
}

// ---------------------------------------------------------------------------
// Conv2 GEMM (wmma, per-k16 flush): grid (4, 32, 4 ksplit), 128 thr. -> g_p2
// ---------------------------------------------------------------------------
__global__ __launch_bounds__(128) void conv2_mma() {
    extern __shared__ char smem[];
    const unsigned smb = (unsigned)__cvta_generic_to_shared(smem);
    const int tid = threadIdx.x, wid = tid >> 5;
    const int octile = blockIdx.x, b = blockIdx.y, ks = blockIdx.z;

    float sums[2][4][8];
#pragma unroll
    for (int mt = 0; mt < 2; ++mt)
#pragma unroll
        for (int nt = 0; nt < 4; ++nt)
#pragma unroll
            for (int e = 0; e < 8; ++e) sums[mt][nt][e] = 0.f;

    auto stage = [&](int ci, int buf) {
        int tap = ks * 36 + (ci >> 3), icc = ci & 7;
        int tt = tap / 9, dh = (tap % 9) / 3, dw = tap % 3;
        unsigned bb = smb + (unsigned)buf * CBUF;
        size_t koff = (size_t)tap * 512 + icc * 64;
        const __nv_bfloat16* ah = g_w2h + (size_t)(octile * 128) * K2_ + koff;
        const __nv_bfloat16* am = g_w2m + (size_t)(octile * 128) * K2_ + koff;
        const __nv_bfloat16* al = g_w2l + (size_t)(octile * 128) * K2_ + koff;
        for (int i = tid; i < 1024; i += 128) {
            int r = i >> 3, c = i & 7;
            unsigned d = (unsigned)(r * 144 + c * 16);
            size_t so = (size_t)r * K2_ + c * 8;
            cpa16(bb + SA_H + d, ah + so);
            cpa16(bb + SA_M + d, am + so);
            cpa16(bb + SA_L + d, al + so);
        }
        size_t xoff = ((size_t)(b * 16 + tt) * 100) * 512 + icc * 64;
        for (int i = tid; i < 512; i += 128) {
            int n = i >> 3, c = i & 7;
            int h = n >> 3, w = n & 7;
            size_t so = xoff + (size_t)((h + dh) * 10 + (w + dw)) * 512 + c * 8;
            unsigned d = (unsigned)(n * 144 + c * 16);
            cpa16(bb + SB_H + d, g_x2h + so);
            cpa16(bb + SB_M + d, g_x2m + so);
            cpa16(bb + SB_L + d, g_x2l + so);
        }
    };

    auto comp = [&](int buf) {
        char* base = smem + (size_t)buf * CBUF;
        const __nv_bfloat16* pah = (const __nv_bfloat16*)(base + SA_H);
        const __nv_bfloat16* pam = (const __nv_bfloat16*)(base + SA_M);
        const __nv_bfloat16* pal = (const __nv_bfloat16*)(base + SA_L);
        const __nv_bfloat16* pbh = (const __nv_bfloat16*)(base + SB_H);
        const __nv_bfloat16* pbm = (const __nv_bfloat16*)(base + SB_M);
        const __nv_bfloat16* pbl = (const __nv_bfloat16*)(base + SB_L);
        FragC tf;
#pragma unroll
        for (int k16 = 0; k16 < 4; ++k16) {
            int ko = k16 * 16;
#pragma unroll
            for (int mt = 0; mt < 2; ++mt) {
                int ar = (wid * 32 + mt * 16) * LDMA + ko;
                FragA ah, am, al;
                wmma::load_matrix_sync(ah, pah + ar, LDMA);
                wmma::load_matrix_sync(am, pam + ar, LDMA);
                wmma::load_matrix_sync(al, pal + ar, LDMA);
#pragma unroll
                for (int nt = 0; nt < 4; ++nt) {
                    int br = (nt * 16) * LDMA + ko;
                    FragB bh, bm, bl;
                    wmma::load_matrix_sync(bh, pbh + br, LDMA);
                    wmma::load_matrix_sync(bm, pbm + br, LDMA);
                    wmma::load_matrix_sync(bl, pbl + br, LDMA);
                    mma6_flush(sums[mt][nt], tf, ah, am, al, bh, bm, bl);
                }
            }
        }
    };

    stage(0, 0); cpcommit();
    stage(1, 1); cpcommit();
#pragma unroll 1
    for (int ci = 0; ci < NC2; ++ci) {
        if (ci + 1 < NC2) cpwait1(); else cpwait0();
        __syncthreads();
        comp(ci & 1);
        __syncthreads();
        if (ci + 2 < NC2) { stage(ci + 2, ci & 1); cpcommit(); }
    }

    __syncthreads();
    float* st = (float*)smem;
    {
        FragC of;
#pragma unroll
        for (int mt = 0; mt < 2; ++mt)
#pragma unroll
            for (int nt = 0; nt < 4; ++nt) {
#pragma unroll
                for (int e = 0; e < of.num_elements; ++e) of.x[e] = sums[mt][nt][e];
                wmma::store_matrix_sync(st + (wid * 32 + mt * 16) * 64 + nt * 16,
                                        of, 64, wmma::mem_row_major);
            }
    }
    __syncthreads();
    for (int e = tid; e < 8192; e += 128) {
        int row = e >> 6, n = e & 63;
        int h = n >> 3, w = n & 7;
        if (h < 7 && w < 7) {
            int oc = octile * 128 + row;
            g_p2[((size_t)(ks * 32 + b) * 512 + oc) * 49 + h * 7 + w] = st[e];
        }
    }
}

// ---------------------------------------------------------------------------
// Heads: reduce conv2 partials (+bias,relu), 1x1 convs, softmax, decode+clip.
// ---------------------------------------------------------------------------
__global__ __launch_bounds__(256) void heads_k(const float* __restrict__ cw,
                                               const float* __restrict__ cb,
                                               const float* __restrict__ bw,
                                               const float* __restrict__ bb,
                                               const float* __restrict__ b2,
                                               const float* __restrict__ info,
                                               float* __restrict__ out) {
    extern __shared__ float sm[];
    float* sf = sm;          // [512][49]
    float* ss = sm + 25088;  // [54][49]

    int b = blockIdx.x, tid = threadIdx.x;
    const float* p0 = g_p2 + (size_t)b * 25088;
    const float* p1 = g_p2 + (size_t)(32 + b) * 25088;
    const float* p2 = g_p2 + (size_t)(64 + b) * 25088;
    const float* p3 = g_p2 + (size_t)(96 + b) * 25088;
    for (int i = tid; i < 25088; i += 256)
        sf[i] = fmaxf((p0[i] + p1[i]) + (p2[i] + p3[i]) + b2[i / 49], 0.f);
    __syncthreads();

    for (int idx = tid; idx < 54 * 49; idx += 256) {
        int o = idx / 49, p = idx - o * 49;
        const float* wr = (o < 18) ? &cw[o * 512] : &bw[(o - 18) * 512];
        float bia = (o < 18) ? cb[o] : bb[o - 18];
        float a = 0.f;
        for (int c = 0; c < 512; ++c) a += sf[c * 49 + p] * __ldg(&wr[c]);
        ss[idx] = a + bia;
    }
    __syncthreads();

    for (int idx = tid; idx < 441; idx += 256) {
        int a9 = idx / 49, p = idx - a9 * 49;
        float bg = ss[a9 * 49 + p], fg = ss[(9 + a9) * 49 + p];
        float m = fmaxf(bg, fg);
        float e0 = expf(bg - m), e1 = expf(fg - m);
        float s = e0 + e1;
        out[CLS_OFF + b * 882 + a9 * 49 + p] = e0 / s;
        out[CLS_OFF + b * 882 + (9 + a9) * 49 + p] = e1 / s;
        g_scr[b * 441 + p * 9 + a9] = e1 / s;
    }
    for (int idx = tid; idx < 36 * 49; idx += 256)
        out[BBOX_OFF + b * 1764 + idx] = ss[882 + idx];

    float imh = info[b * 3 + 0], imw = info[b * 3 + 1];
    for (int i = tid; i < 441; i += 256) {
        int k = i / 9, a = i - k * 9;
        int hp = k / 7, wp = k - hp * 7;
        float d0 = ss[(18 + a * 4 + 0) * 49 + k];
        float d1 = ss[(18 + a * 4 + 1) * 49 + k];
        float d2 = ss[(18 + a * 4 + 2) * 49 + k];
        float d3 = ss[(18 + a * 4 + 3) * 49 + k];
        float x1 = c_anch[a][0] + wp * 16.f, y1 = c_anch[a][1] + hp * 16.f;
        float x2 = c_anch[a][2] + wp * 16.f, y2 = c_anch[a][3] + hp * 16.f;
        float aw = x2 - x1 + 1.f, ah = y2 - y1 + 1.f;
        float cx = x1 + 0.5f * aw, cy = y1 + 0.5f * ah;
        float pcx = d0 * aw + cx, pcy = d1 * ah + cy;
        float pw = expf(d2) * aw, phh = expf(d3) * ah;
        float bx1 = fminf(fmaxf(pcx - 0.5f * pw, 0.f), imw - 1.f);
        float by1 = fminf(fmaxf(pcy - 0.5f * phh, 0.f), imh - 1.f);
        float bx2 = fminf(fmaxf(pcx + 0.5f * pw, 0.f), imw - 1.f);
        float by2 = fminf(fmaxf(pcy + 0.5f * phh, 0.f), imh - 1.f);
        float* pr = &g_prop[(b * 441 + i) * 4];
        pr[0] = bx1; pr[1] = by1; pr[2] = bx2; pr[3] = by2;
    }
}

// ---------------------------------------------------------------------------
// NMS: stable rank-sort (score desc, idx asc), greedy, compact.
// ---------------------------------------------------------------------------
__global__ __launch_bounds__(448) void nms_k(float* __restrict__ out) {
    __shared__ float ux1[441], uy1[441], ux2[441], uy2[441], usc[441];
    __shared__ float sx1[441], sy1[441], sx2[441], sy2[441], sar[441];
    __shared__ int keep[441];

    int b = blockIdx.x, tid = threadIdx.x;
    for (int i = tid; i < 441; i += 448) {
        const float* pr = &g_prop[(b * 441 + i) * 4];
        ux1[i] = pr[0]; uy1[i] = pr[1]; ux2[i] = pr[2]; uy2[i] = pr[3];
        usc[i] = g_scr[b * 441 + i];
        keep[i] = 1;
    }
    __syncthreads();

    for (int i = tid; i < 441; i += 448) {
        float si = usc[i];
        int r = 0;
        for (int j = 0; j < 441; ++j) {
            float sj = usc[j];
            r += (sj > si) || (sj == si && j < i);
        }
        sx1[r] = ux1[i]; sy1[r] = uy1[i]; sx2[r] = ux2[i]; sy2[r] = uy2[i];
        sar[r] = (ux2[i] - ux1[i] + 1.f) * (uy2[i] - uy1[i] + 1.f);
    }

    for (int i = 0; i < 440; ++i) {
        __syncthreads();
        if (keep[i]) {
            float xi1 = sx1[i], yi1 = sy1[i], xi2 = sx2[i], yi2 = sy2[i], ai = sar[i];
            for (int j = i + 1 + tid; j < 441; j += 448) {
                if (!keep[j]) continue;
                float xx1 = fmaxf(xi1, sx1[j]);
                float yy1 = fmaxf(yi1, sy1[j]);
                float xx2 = fminf(xi2, sx2[j]);
                float yy2 = fminf(yi2, sy2[j]);
                float iw = fmaxf(xx2 - xx1 + 1.f, 0.f);
                float ih = fmaxf(yy2 - yy1 + 1.f, 0.f);
                float inter = iw * ih;
                float iou = inter / (ai + sar[j] - inter);
                if (iou > 0.7f) keep[j] = 0;
            }
        }
    }
    __syncthreads();

    for (int r = tid; r < 300; r += 448) {
        float* o = &out[ROIS_OFF + (b * 300 + r) * 5];
        o[0] = (float)b; o[1] = 0.f; o[2] = 0.f; o[3] = 0.f; o[4] = 0.f;
    }
    __syncthreads();
    for (int i = tid; i < 441; i += 448) {
        if (keep[i]) {
            int pos = 0;
            for (int j = 0; j < i; ++j) pos += keep[j];
            if (pos < 300) {
                float* o = &out[ROIS_OFF + (b * 300 + pos) * 5];
                o[1] = sx1[i]; o[2] = sy1[i]; o[3] = sx2[i]; o[4] = sy2[i];
            }
        }
    }
}

// ---------------------------------------------------------------------------
// Launch
// ---------------------------------------------------------------------------
extern "C" void kernel_launch(void* const* d_in, const int* in_sizes, int n_in,
                              void* d_out, int out_size) {
    const float* base = (const float*)d_in[0];
    const float* info = (const float*)d_in[1];
    const float* w1   = (const float*)d_in[4];
    const float* b1   = (const float*)d_in[5];
    const float* w2   = (const float*)d_in[6];
    const float* b2   = (const float*)d_in[7];
    const float* cw   = (const float*)d_in[8];
    const float* cb   = (const float*)d_in[9];
    const float* bw   = (const float*)d_in[10];
    const float* bb   = (const float*)d_in[11];
    float* out = (float*)d_out;

    cudaFuncSetAttribute(conv1_mma, cudaFuncAttributeMaxDynamicSharedMemorySize, SMEM_CONV);
    cudaFuncSetAttribute(conv2_mma, cudaFuncAttributeMaxDynamicSharedMemorySize, SMEM_CONV);
    cudaFuncSetAttribute(heads_k,   cudaFuncAttributeMaxDynamicSharedMemorySize, 110936);

    __nv_bfloat16 *pw1h, *pw1m, *pw1l, *pw2h, *pw2m, *pw2l;
    cudaGetSymbolAddress((void**)&pw1h, g_w1h);
    cudaGetSymbolAddress((void**)&pw1m, g_w1m);
    cudaGetSymbolAddress((void**)&pw1l, g_w1l);
    cudaGetSymbolAddress((void**)&pw2h, g_w2h);
    cudaGetSymbolAddress((void**)&pw2m, g_w2m);
    cudaGetSymbolAddress((void**)&pw2l, g_w2l);

    prep_w<<<dim3(512, 8), 256>>>(w1, pw1h, pw1m, pw1l, 27);
    prep_w<<<dim3(512, 8), 256>>>(w2, pw2h, pw2m, pw2l, 144);
    zero_x1k<<<14400, 256>>>();
    zero_x2k<<<12800, 256>>>();
    prep_x1<<<dim3(32, 16, 8), 256>>>(base);
    conv1_mma<<<dim3(4, 512), 128, SMEM_CONV>>>(b1);
    conv2_mma<<<dim3(4, 32, 4), 128, SMEM_CONV>>>();
    heads_k<<<32, 256, 110936>>>(cw, cb, bw, bb, b2, info, out);
    nms_k<<<32, 448>>>(out);
}